// round 1
// baseline (speedup 1.0000x reference)
#include <cuda_runtime.h>
#include <cuda_bf16.h>
#include <stdint.h>
#include <math.h>

#define LAYERS_   10
#define NL_       40
#define RC_       32
#define DC_       32
#define SC_       256
#define EC_       256
#define CL_       256
#define B_        8
#define T_        16384
#define BT_       131072   /* B_*T_ */

// ---------------- scratch (static device globals; no allocations) -------------
__device__ float g_h[32 * BT_];                       // residual state, [c][BT]
__device__ float g_z[167772160];                      // 40*32*BT, [layer][c][BT]
__device__ float g_skip[SC_ * BT_];                   // [c][BT]
__device__ float g_out1[EC_ * BT_];                   // [c][BT]
__device__ float g_skipb[SC_];

// ---------------- small helpers ----------------
__device__ __forceinline__ unsigned f2tf(float x) {
    unsigned r;
    asm("cvt.rna.tf32.f32 %0, %1;" : "=r"(r) : "f"(x));
    return r;
}
__device__ __forceinline__ void mma8(float* d, const unsigned* a, const unsigned* b) {
    asm volatile(
        "mma.sync.aligned.m16n8k8.row.col.f32.tf32.tf32.f32 "
        "{%0,%1,%2,%3},{%4,%5,%6,%7},{%8,%9},{%0,%1,%2,%3};\n"
        : "+f"(d[0]), "+f"(d[1]), "+f"(d[2]), "+f"(d[3])
        : "r"(a[0]), "r"(a[1]), "r"(a[2]), "r"(a[3]), "r"(b[0]), "r"(b[1]));
}

// ---------------- bias reduction for skip ----------------
__global__ void k_bias(const float* __restrict__ skip_b) {
    int o = threadIdx.x;
    float s = 0.f;
#pragma unroll 1
    for (int i = 0; i < NL_; i++) s += skip_b[i * SC_ + o];
    g_skipb[o] = s;
}

// ---------------- input 1x1 conv: x[8,256,16384] -> h[32][BT] ----------------
__global__ __launch_bounds__(256) void k_input(const float* __restrict__ x,
                                               const float* __restrict__ w_in,
                                               const float* __restrict__ b_in) {
    __shared__ float ws[256 * 32];   // [c][rc]
    __shared__ float bs[32];
    int tid = threadIdx.x;
    for (int e = tid; e < 256 * 32; e += 256) {
        int c = e >> 5, rc = e & 31;
        ws[e] = w_in[rc * 256 + c];
    }
    if (tid < 32) bs[tid] = b_in[tid];
    __syncthreads();

    int i0 = blockIdx.x * 512 + tid;
    int i1 = i0 + 256;
    int b0 = i0 >> 14, t0 = i0 & (T_ - 1);
    int b1 = i1 >> 14, t1 = i1 & (T_ - 1);
    const float* x0 = x + (size_t)b0 * 256 * T_ + t0;
    const float* x1 = x + (size_t)b1 * 256 * T_ + t1;

    float a0[32], a1[32];
#pragma unroll
    for (int r = 0; r < 32; r++) { a0[r] = bs[r]; a1[r] = bs[r]; }

#pragma unroll 1
    for (int c = 0; c < 256; c++) {
        float xv0 = x0[(size_t)c * T_];
        float xv1 = x1[(size_t)c * T_];
        const float* w = &ws[c * 32];
#pragma unroll
        for (int r = 0; r < 32; r++) {
            a0[r] = fmaf(w[r], xv0, a0[r]);
            a1[r] = fmaf(w[r], xv1, a1[r]);
        }
    }
#pragma unroll
    for (int r = 0; r < 32; r++) {
        g_h[r * BT_ + i0] = a0[r];
        g_h[r * BT_ + i1] = a1[r];
    }
}

// ---------------- per-layer z = tanh(filt)*sigmoid(gate) ----------------
__global__ __launch_bounds__(256) void k_z(const float* __restrict__ filt_w,
                                           const float* __restrict__ filt_b,
                                           const float* __restrict__ gate_w,
                                           const float* __restrict__ gate_b,
                                           int layer, int dil) {
    __shared__ float s_fw0[1024], s_fw1[1024], s_gw0[1024], s_gw1[1024];  // [c][o]
    __shared__ float s_fb[32], s_gb[32];
    int tid = threadIdx.x;
    {
        const float* fwL = filt_w + layer * 2048;
        const float* gwL = gate_w + layer * 2048;
        for (int e = tid; e < 1024; e += 256) {
            int c = e >> 5, o = e & 31;
            int src = (o * 32 + c) * 2;
            s_fw0[c * 32 + o] = fwL[src];
            s_fw1[c * 32 + o] = fwL[src + 1];
            s_gw0[c * 32 + o] = gwL[src];
            s_gw1[c * 32 + o] = gwL[src + 1];
        }
        if (tid < 32) {
            s_fb[tid] = filt_b[layer * 32 + tid];
            s_gb[tid] = gate_b[layer * 32 + tid];
        }
    }
    __syncthreads();

    int i0 = blockIdx.x * 512 + tid;
    int i1 = i0 + 256;
    bool v0 = (i0 & (T_ - 1)) >= dil;
    bool v1 = (i1 & (T_ - 1)) >= dil;

    float fa0[32], fa1[32], ga0[32], ga1[32];
#pragma unroll
    for (int o = 0; o < 32; o++) { fa0[o] = 0.f; fa1[o] = 0.f; ga0[o] = 0.f; ga1[o] = 0.f; }

#pragma unroll 1
    for (int c = 0; c < 32; c++) {
        const float* hrow = g_h + c * BT_;
        float hc0 = hrow[i0], hc1 = hrow[i1];
        float hp0 = v0 ? hrow[i0 - dil] : 0.f;
        float hp1 = v1 ? hrow[i1 - dil] : 0.f;
        const float* wf0 = s_fw0 + c * 32;
        const float* wf1 = s_fw1 + c * 32;
        const float* wg0 = s_gw0 + c * 32;
        const float* wg1 = s_gw1 + c * 32;
#pragma unroll
        for (int o = 0; o < 32; o++) {
            float f0w = wf0[o], f1w = wf1[o], g0w = wg0[o], g1w = wg1[o];
            fa0[o] = fmaf(f0w, hp0, fa0[o]); fa0[o] = fmaf(f1w, hc0, fa0[o]);
            fa1[o] = fmaf(f0w, hp1, fa1[o]); fa1[o] = fmaf(f1w, hc1, fa1[o]);
            ga0[o] = fmaf(g0w, hp0, ga0[o]); ga0[o] = fmaf(g1w, hc0, ga0[o]);
            ga1[o] = fmaf(g0w, hp1, ga1[o]); ga1[o] = fmaf(g1w, hc1, ga1[o]);
        }
    }

#pragma unroll
    for (int o = 0; o < 32; o++) {
        float fx0 = fa0[o] + s_fb[o];
        float ef0 = __expf(-2.f * fabsf(fx0));
        float th0 = copysignf(__fdividef(1.f - ef0, 1.f + ef0), fx0);
        float sg0 = __fdividef(1.f, 1.f + __expf(-(ga0[o] + s_gb[o])));
        float z0 = th0 * sg0;

        float fx1 = fa1[o] + s_fb[o];
        float ef1 = __expf(-2.f * fabsf(fx1));
        float th1 = copysignf(__fdividef(1.f - ef1, 1.f + ef1), fx1);
        float sg1 = __fdividef(1.f, 1.f + __expf(-(ga1[o] + s_gb[o])));
        float z1 = th1 * sg1;

        float* zrow = g_z + ((size_t)layer * 32 + o) * BT_;
        zrow[i0] = z0;
        zrow[i1] = z1;
    }
}

// ---------------- per-layer residual update: h += conv(z, res_w, d) ----------------
__global__ __launch_bounds__(256) void k_res(const float* __restrict__ res_w,
                                             const float* __restrict__ res_b,
                                             int layer, int dil) {
    __shared__ float s_w0[1024], s_w1[1024];  // [c][o]
    __shared__ float s_b[32];
    int tid = threadIdx.x;
    {
        const float* wL = res_w + layer * 2048;
        for (int e = tid; e < 1024; e += 256) {
            int c = e >> 5, o = e & 31;
            int src = (o * 32 + c) * 2;
            s_w0[c * 32 + o] = wL[src];
            s_w1[c * 32 + o] = wL[src + 1];
        }
        if (tid < 32) s_b[tid] = res_b[layer * 32 + tid];
    }
    __syncthreads();

    int i0 = blockIdx.x * 512 + tid;
    int i1 = i0 + 256;
    bool v0 = (i0 & (T_ - 1)) >= dil;
    bool v1 = (i1 & (T_ - 1)) >= dil;

    float a0[32], a1[32];
#pragma unroll
    for (int o = 0; o < 32; o++) { a0[o] = 0.f; a1[o] = 0.f; }

#pragma unroll 1
    for (int c = 0; c < 32; c++) {
        const float* zrow = g_z + ((size_t)layer * 32 + c) * BT_;
        float zc0 = zrow[i0], zc1 = zrow[i1];
        float zp0 = v0 ? zrow[i0 - dil] : 0.f;
        float zp1 = v1 ? zrow[i1 - dil] : 0.f;
        const float* w0 = s_w0 + c * 32;
        const float* w1 = s_w1 + c * 32;
#pragma unroll
        for (int o = 0; o < 32; o++) {
            float w0v = w0[o], w1v = w1[o];
            a0[o] = fmaf(w0v, zp0, a0[o]); a0[o] = fmaf(w1v, zc0, a0[o]);
            a1[o] = fmaf(w0v, zp1, a1[o]); a1[o] = fmaf(w1v, zc1, a1[o]);
        }
    }
#pragma unroll
    for (int o = 0; o < 32; o++) {
        float* hrow = g_h + o * BT_;
        hrow[i0] = hrow[i0] + a0[o] + s_b[o];
        hrow[i1] = hrow[i1] + a1[o] + s_b[o];
    }
}

// ---------------- deferred skip GEMM: skip = W[256x2560] * Zgather + bias ----------------
// tf32 mma: CTA tile 128(M) x 128(N tokens); 8 warps as 4x2; warp tile 32x64.
#define SA_STR 36
#define SB_STR 136

__global__ __launch_bounds__(256) void k_skip(const float* __restrict__ skip_w) {
    __shared__ unsigned smem_u[128 * SA_STR + 32 * SB_STR];  // 8960 words
    unsigned* sA = smem_u;
    unsigned* sB = smem_u + 128 * SA_STR;

    int tid = threadIdx.x;
    int warp = tid >> 5, lane = tid & 31;
    int grp = lane >> 2, tig = lane & 3;
    int m_base = blockIdx.y * 128;
    int t0 = blockIdx.x * 128;
    int m_off = (warp >> 1) * 32;
    int n_off = (warp & 1) * 64;

    float acc[2][8][4];
#pragma unroll
    for (int mf = 0; mf < 2; mf++)
#pragma unroll
        for (int nf = 0; nf < 8; nf++)
#pragma unroll
            for (int q = 0; q < 4; q++) acc[mf][nf][q] = 0.f;

#pragma unroll 1
    for (int step = 0; step < 2 * NL_; step++) {
        int li = step >> 1;
        int tap = step & 1;
        int dil = 1 << (li % LAYERS_);
        int shift = (tap == 0) ? dil : 0;

        // stage A: weights [128 out][32 in] for (li, tap)
#pragma unroll 4
        for (int j = 0; j < 16; j++) {
            int e = tid + j * 256;
            int r = e >> 5, c = e & 31;
            float w = skip_w[(((size_t)li * SC_ + m_base + r) * 32 + c) * 2 + tap];
            sA[r * SA_STR + c] = f2tf(w);
        }
        // stage B: z [32 in][128 tokens], shifted by dilation, zero-padded per batch
#pragma unroll 4
        for (int j = 0; j < 16; j++) {
            int e = tid + j * 256;
            int c = e >> 7, t = e & 127;
            int g = t0 + t;
            float v = 0.f;
            if ((g & (T_ - 1)) >= shift) v = g_z[((size_t)li * 32 + c) * BT_ + g - shift];
            sB[c * SB_STR + t] = f2tf(v);
        }
        __syncthreads();

#pragma unroll
        for (int kc = 0; kc < 32; kc += 8) {
            unsigned a[2][4], b[8][2];
#pragma unroll
            for (int mf = 0; mf < 2; mf++) {
                int r = m_off + mf * 16 + grp;
                a[mf][0] = sA[r * SA_STR + kc + tig];
                a[mf][1] = sA[(r + 8) * SA_STR + kc + tig];
                a[mf][2] = sA[r * SA_STR + kc + tig + 4];
                a[mf][3] = sA[(r + 8) * SA_STR + kc + tig + 4];
            }
#pragma unroll
            for (int nf = 0; nf < 8; nf++) {
                int cidx = n_off + nf * 8 + grp;
                b[nf][0] = sB[(kc + tig) * SB_STR + cidx];
                b[nf][1] = sB[(kc + tig + 4) * SB_STR + cidx];
            }
#pragma unroll
            for (int mf = 0; mf < 2; mf++)
#pragma unroll
                for (int nf = 0; nf < 8; nf++) mma8(acc[mf][nf], a[mf], b[nf]);
        }
        __syncthreads();
    }

#pragma unroll
    for (int mf = 0; mf < 2; mf++)
#pragma unroll
        for (int nf = 0; nf < 8; nf++) {
            int row0 = m_off + mf * 16 + grp;
            int col0 = n_off + nf * 8 + 2 * tig;
            float bias0 = g_skipb[m_base + row0];
            float bias1 = g_skipb[m_base + row0 + 8];
            size_t p0 = (size_t)(m_base + row0) * BT_ + t0 + col0;
            size_t p2 = (size_t)(m_base + row0 + 8) * BT_ + t0 + col0;
            g_skip[p0] = acc[mf][nf][0] + bias0;
            g_skip[p0 + 1] = acc[mf][nf][1] + bias0;
            g_skip[p2] = acc[mf][nf][2] + bias1;
            g_skip[p2 + 1] = acc[mf][nf][3] + bias1;
        }
}

// ---------------- end1 / end2 GEMMs (relu on input), STAGE=1: skip->out1, STAGE=2: out1->d_out^T
template <int STAGE>
__global__ __launch_bounds__(256) void k_end(const float* __restrict__ W,
                                             const float* __restrict__ bvec,
                                             float* __restrict__ dout) {
    __shared__ unsigned smem_u[128 * SA_STR + 32 * SB_STR];
    unsigned* sA = smem_u;
    unsigned* sB = smem_u + 128 * SA_STR;

    int tid = threadIdx.x;
    int warp = tid >> 5, lane = tid & 31;
    int grp = lane >> 2, tig = lane & 3;
    int m_base = blockIdx.y * 128;
    int t0 = blockIdx.x * 128;
    int m_off = (warp >> 1) * 32;
    int warp_n = warp & 1;
    int n_off = warp_n * 64;

    const float* gin = (STAGE == 1) ? g_skip : g_out1;

    float acc[2][8][4];
#pragma unroll
    for (int mf = 0; mf < 2; mf++)
#pragma unroll
        for (int nf = 0; nf < 8; nf++)
#pragma unroll
            for (int q = 0; q < 4; q++) acc[mf][nf][q] = 0.f;

#pragma unroll 1
    for (int step = 0; step < 8; step++) {
        int kc0 = step * 32;
#pragma unroll 4
        for (int j = 0; j < 16; j++) {
            int e = tid + j * 256;
            int r = e >> 5, c = e & 31;
            sA[r * SA_STR + c] = f2tf(W[(size_t)(m_base + r) * 256 + kc0 + c]);
        }
#pragma unroll 4
        for (int j = 0; j < 16; j++) {
            int e = tid + j * 256;
            int c = e >> 7, t = e & 127;
            float v = gin[(size_t)(kc0 + c) * BT_ + t0 + t];
            v = fmaxf(v, 0.f);  // relu on input (both stages)
            sB[c * SB_STR + t] = f2tf(v);
        }
        __syncthreads();
#pragma unroll
        for (int kc = 0; kc < 32; kc += 8) {
            unsigned a[2][4], b[8][2];
#pragma unroll
            for (int mf = 0; mf < 2; mf++) {
                int r = m_off + mf * 16 + grp;
                a[mf][0] = sA[r * SA_STR + kc + tig];
                a[mf][1] = sA[(r + 8) * SA_STR + kc + tig];
                a[mf][2] = sA[r * SA_STR + kc + tig + 4];
                a[mf][3] = sA[(r + 8) * SA_STR + kc + tig + 4];
            }
#pragma unroll
            for (int nf = 0; nf < 8; nf++) {
                int cidx = n_off + nf * 8 + grp;
                b[nf][0] = sB[(kc + tig) * SB_STR + cidx];
                b[nf][1] = sB[(kc + tig + 4) * SB_STR + cidx];
            }
#pragma unroll
            for (int mf = 0; mf < 2; mf++)
#pragma unroll
                for (int nf = 0; nf < 8; nf++) mma8(acc[mf][nf], a[mf], b[nf]);
        }
        __syncthreads();
    }

    if (STAGE == 1) {
        // channel-major write to g_out1
#pragma unroll
        for (int mf = 0; mf < 2; mf++)
#pragma unroll
            for (int nf = 0; nf < 8; nf++) {
                int row0 = m_off + mf * 16 + grp;
                int col0 = n_off + nf * 8 + 2 * tig;
                float bias0 = bvec[m_base + row0];
                float bias1 = bvec[m_base + row0 + 8];
                size_t p0 = (size_t)(m_base + row0) * BT_ + t0 + col0;
                size_t p2 = (size_t)(m_base + row0 + 8) * BT_ + t0 + col0;
                g_out1[p0] = acc[mf][nf][0] + bias0;
                g_out1[p0 + 1] = acc[mf][nf][1] + bias0;
                g_out1[p2] = acc[mf][nf][2] + bias1;
                g_out1[p2 + 1] = acc[mf][nf][3] + bias1;
            }
    } else {
        // transpose to token-major d_out[(token)*256 + ch] via shared memory
        float* ts = (float*)smem_u;  // [64 tokens][132]
#pragma unroll 1
        for (int half = 0; half < 2; half++) {
            __syncthreads();
            if (warp_n == half) {
#pragma unroll
                for (int mf = 0; mf < 2; mf++)
#pragma unroll
                    for (int nf = 0; nf < 8; nf++) {
                        int rowL = m_off + mf * 16 + grp;
                        int colL = nf * 8 + 2 * tig;  // 0..63 within half
                        float bias0 = bvec[m_base + rowL];
                        float bias1 = bvec[m_base + rowL + 8];
                        ts[colL * 132 + rowL] = acc[mf][nf][0] + bias0;
                        ts[(colL + 1) * 132 + rowL] = acc[mf][nf][1] + bias0;
                        ts[colL * 132 + rowL + 8] = acc[mf][nf][2] + bias1;
                        ts[(colL + 1) * 132 + rowL + 8] = acc[mf][nf][3] + bias1;
                    }
            }
            __syncthreads();
            // write 64 tokens x 128 channels, coalesced float4 per token row
#pragma unroll
            for (int pass = 0; pass < 8; pass++) {
                int tk = pass * 8 + (tid >> 5);
                float4 v = *(const float4*)&ts[tk * 132 + lane * 4];
                *(float4*)&dout[(size_t)(t0 + half * 64 + tk) * 256 + m_base + lane * 4] = v;
            }
        }
    }
}

// ---------------- host launcher ----------------
extern "C" void kernel_launch(void* const* d_in, const int* in_sizes, int n_in,
                              void* d_out, int out_size) {
    const float* x      = (const float*)d_in[0];
    const float* w_in   = (const float*)d_in[1];
    const float* b_in   = (const float*)d_in[2];
    const float* filt_w = (const float*)d_in[3];
    const float* filt_b = (const float*)d_in[4];
    const float* gate_w = (const float*)d_in[5];
    const float* gate_b = (const float*)d_in[6];
    const float* res_w  = (const float*)d_in[7];
    const float* res_b  = (const float*)d_in[8];
    const float* skip_w = (const float*)d_in[9];
    const float* skip_b = (const float*)d_in[10];
    const float* end1_w = (const float*)d_in[11];
    const float* end1_b = (const float*)d_in[12];
    const float* end2_w = (const float*)d_in[13];
    const float* end2_b = (const float*)d_in[14];
    float* out = (float*)d_out;

    k_bias<<<1, 256>>>(skip_b);
    k_input<<<BT_ / 512, 256>>>(x, w_in, b_in);

    for (int i = 0; i < NL_; i++) {
        int d = 1 << (i % LAYERS_);
        k_z<<<BT_ / 512, 256>>>(filt_w, filt_b, gate_w, gate_b, i, d);
        k_res<<<BT_ / 512, 256>>>(res_w, res_b, i, d);
    }

    dim3 gg(BT_ / 128, 2);
    k_skip<<<gg, 256>>>(skip_w);
    k_end<1><<<gg, 256>>>(end1_w, end1_b, nullptr);
    k_end<2><<<gg, 256>>>(end2_w, end2_b, out);
}